// round 1
// baseline (speedup 1.0000x reference)
#include <cuda_runtime.h>
#include <math.h>

// ---------------------------------------------------------------------------
// SelfAttention: out = softmax((Q K^T)/sqrt(Dh)) V  with fused QKV + out proj
// B=4, S=2048, D=1024, H=16, Dh=64.  kqv chunk order per reference: k, q, v.
// ---------------------------------------------------------------------------

#define B_DIM 4
#define S_DIM 2048
#define D_DIM 1024
#define H_DIM 16
#define DH_DIM 64

// scratch (allocation-free rule: __device__ globals)
__device__ float g_kqv[B_DIM * S_DIM * 3 * D_DIM];   // [B,S,3D]  ~100.7 MB
__device__ float g_attn[B_DIM * S_DIM * D_DIM];      // [B,S,D]   ~33.6 MB

// ---------------------------------------------------------------------------
// GEMM: C[M,N] = A[M,K] @ B[K,N] + bias[N]
// 128x128 block tile, BK=16, 256 threads, 8x8 per thread (split-tile 4+4)
// ---------------------------------------------------------------------------
__global__ void __launch_bounds__(256)
gemm_bias_kernel(const float* __restrict__ A, const float* __restrict__ Bmat,
                 const float* __restrict__ bias, float* __restrict__ C,
                 int M, int N, int K)
{
    const int BM = 128, BN = 128, BK = 16;
    __shared__ float As[16][132];   // [k][m], padded
    __shared__ float Bs[16][128];   // [k][n]

    const int tid  = threadIdx.x;
    const int row0 = blockIdx.y * BM;
    const int col0 = blockIdx.x * BN;
    const int tm = tid >> 4;        // 0..15
    const int tn = tid & 15;        // 0..15

    float acc[8][8];
    #pragma unroll
    for (int i = 0; i < 8; i++)
        #pragma unroll
        for (int j = 0; j < 8; j++) acc[i][j] = 0.f;

    for (int k0 = 0; k0 < K; k0 += BK) {
        // A tile: 128x16 -> transposed into As[k][m]; 512 float4 loads
        #pragma unroll
        for (int i = 0; i < 2; i++) {
            int lin = tid + i * 256;           // 0..511
            int r   = lin >> 2;                // 0..127
            int kc  = (lin & 3) << 2;          // 0,4,8,12
            float4 v = *(const float4*)&A[(size_t)(row0 + r) * K + k0 + kc];
            As[kc + 0][r] = v.x;
            As[kc + 1][r] = v.y;
            As[kc + 2][r] = v.z;
            As[kc + 3][r] = v.w;
        }
        // B tile: 16x128, direct
        #pragma unroll
        for (int i = 0; i < 2; i++) {
            int lin = tid + i * 256;
            int kr  = lin >> 5;                // 0..15
            int nc  = (lin & 31) << 2;         // 0..124
            *(float4*)&Bs[kr][nc] =
                *(const float4*)&Bmat[(size_t)(k0 + kr) * N + col0 + nc];
        }
        __syncthreads();

        #pragma unroll
        for (int kk = 0; kk < BK; kk++) {
            float a[8], b[8];
            *(float4*)&a[0] = *(const float4*)&As[kk][tm * 4];
            *(float4*)&a[4] = *(const float4*)&As[kk][64 + tm * 4];
            *(float4*)&b[0] = *(const float4*)&Bs[kk][tn * 4];
            *(float4*)&b[4] = *(const float4*)&Bs[kk][64 + tn * 4];
            #pragma unroll
            for (int i = 0; i < 8; i++)
                #pragma unroll
                for (int j = 0; j < 8; j++)
                    acc[i][j] += a[i] * b[j];
        }
        __syncthreads();
    }

    // epilogue: bias + store (split-tile column mapping)
    #pragma unroll
    for (int i = 0; i < 8; i++) {
        int r = row0 + ((i < 4) ? (tm * 4 + i) : (64 + tm * 4 + (i - 4)));
        int c0 = col0 + tn * 4;
        int c1 = col0 + 64 + tn * 4;
        float4 v0, v1;
        v0.x = acc[i][0] + bias[c0 + 0];
        v0.y = acc[i][1] + bias[c0 + 1];
        v0.z = acc[i][2] + bias[c0 + 2];
        v0.w = acc[i][3] + bias[c0 + 3];
        v1.x = acc[i][4] + bias[c1 + 0];
        v1.y = acc[i][5] + bias[c1 + 1];
        v1.z = acc[i][6] + bias[c1 + 2];
        v1.w = acc[i][7] + bias[c1 + 3];
        *(float4*)&C[(size_t)r * N + c0] = v0;
        *(float4*)&C[(size_t)r * N + c1] = v1;
    }
}

// ---------------------------------------------------------------------------
// Attention: one CTA = 128 query rows of one (b,h). Online softmax over KV
// tiles of 32. q/o in registers; K/V tiles in smem (broadcast reads);
// scores staged in padded smem so the j-loop can stay rolled.
// ---------------------------------------------------------------------------
__global__ void __launch_bounds__(128)
attn_kernel(const float* __restrict__ kqv, float* __restrict__ out)
{
    const int TK = 32;
    __shared__ float Ks[32][64];     // 8 KB
    __shared__ float Vs[32][64];     // 8 KB
    __shared__ float Ss[128][33];    // padded: bank = (tid + j) % 32

    const int tid  = threadIdx.x;
    const int b    = blockIdx.z;
    const int h    = blockIdx.y;
    const int qrow = blockIdx.x * 128 + tid;
    const int D3   = 3 * D_DIM;
    const float scale = 0.125f;      // 1/sqrt(64)

    // q (chunk order k,q,v -> q at offset D), pre-scaled; o accumulator
    float q[64], o[64];
    {
        const float* qp = kqv + (size_t)(b * S_DIM + qrow) * D3 + D_DIM + h * DH_DIM;
        #pragma unroll
        for (int d = 0; d < 64; d += 4) {
            float4 v = *(const float4*)(qp + d);
            q[d + 0] = v.x * scale; q[d + 1] = v.y * scale;
            q[d + 2] = v.z * scale; q[d + 3] = v.w * scale;
            o[d + 0] = 0.f; o[d + 1] = 0.f; o[d + 2] = 0.f; o[d + 3] = 0.f;
        }
    }

    float m = -1e30f, l = 0.f;

    for (int t0 = 0; t0 < S_DIM; t0 += TK) {
        __syncthreads();   // protect prior-iteration smem reads
        // load K tile (offset 0) and V tile (offset 2D): 512 float4 each half
        #pragma unroll
        for (int i = 0; i < 4; i++) {
            int lin = tid + i * 128;        // 0..511
            int r   = lin >> 4;             // 0..31
            int c   = (lin & 15) << 2;      // 0..60
            size_t base = (size_t)(b * S_DIM + t0 + r) * D3 + h * DH_DIM + c;
            *(float4*)&Ks[r][c] = *(const float4*)(kqv + base);
            *(float4*)&Vs[r][c] = *(const float4*)(kqv + base + 2 * D_DIM);
        }
        __syncthreads();

        // scores for this tile (j uniform -> Ks reads broadcast)
        float mt = -1e30f;
        #pragma unroll 4
        for (int j = 0; j < TK; j++) {
            float acc = 0.f;
            #pragma unroll
            for (int d = 0; d < 64; d += 4) {
                float4 kv = *(const float4*)&Ks[j][d];
                acc += q[d] * kv.x + q[d + 1] * kv.y
                     + q[d + 2] * kv.z + q[d + 3] * kv.w;
            }
            Ss[tid][j] = acc;
            mt = fmaxf(mt, acc);
        }

        // online softmax rescale
        float mn   = fmaxf(m, mt);
        float corr = __expf(m - mn);
        m = mn;
        l *= corr;
        #pragma unroll
        for (int d = 0; d < 64; d++) o[d] *= corr;

        // P @ V (j uniform -> Vs reads broadcast)
        #pragma unroll 2
        for (int j = 0; j < TK; j++) {
            float p = __expf(Ss[tid][j] - mn);
            l += p;
            #pragma unroll
            for (int d = 0; d < 64; d += 4) {
                float4 vv = *(const float4*)&Vs[j][d];
                o[d + 0] += p * vv.x; o[d + 1] += p * vv.y;
                o[d + 2] += p * vv.z; o[d + 3] += p * vv.w;
            }
        }
    }

    float inv = 1.f / l;
    float* op = out + (size_t)(b * S_DIM + qrow) * D_DIM + h * DH_DIM;
    #pragma unroll
    for (int d = 0; d < 64; d += 4) {
        float4 v;
        v.x = o[d + 0] * inv; v.y = o[d + 1] * inv;
        v.z = o[d + 2] * inv; v.w = o[d + 3] * inv;
        *(float4*)(op + d) = v;
    }
}

// ---------------------------------------------------------------------------
extern "C" void kernel_launch(void* const* d_in, const int* in_sizes, int n_in,
                              void* d_out, int out_size)
{
    const float* x     = (const float*)d_in[0];   // [4,2048,1024]
    const float* w_in  = (const float*)d_in[1];   // [1024,3072]
    const float* b_in  = (const float*)d_in[2];   // [3072]
    const float* w_out = (const float*)d_in[3];   // [1024,1024]
    const float* b_out = (const float*)d_in[4];   // [1024]
    float* out = (float*)d_out;

    float *kqv, *attn;
    cudaGetSymbolAddress((void**)&kqv, g_kqv);
    cudaGetSymbolAddress((void**)&attn, g_attn);

    const int M = B_DIM * S_DIM;                  // 8192

    // 1) kqv = x @ w_in + b_in     [8192, 3072]
    {
        dim3 grid(3 * D_DIM / 128, M / 128);
        gemm_bias_kernel<<<grid, 256>>>(x, w_in, b_in, kqv, M, 3 * D_DIM, D_DIM);
    }
    // 2) attention -> g_attn [B,S,D]
    {
        dim3 grid(S_DIM / 128, H_DIM, B_DIM);
        attn_kernel<<<grid, 128>>>(kqv, attn);
    }
    // 3) out = attn @ w_out + b_out  [8192, 1024]
    {
        dim3 grid(D_DIM / 128, M / 128);
        gemm_bias_kernel<<<grid, 256>>>(attn, w_out, b_out, out, M, D_DIM, D_DIM);
    }
}

// round 3
// speedup vs baseline: 1.2268x; 1.2268x over previous
#include <cuda_runtime.h>
#include <math.h>

// ---------------------------------------------------------------------------
// SelfAttention: out = softmax((Q K^T)/sqrt(Dh)) V  with fused QKV + out proj
// B=4, S=2048, D=1024, H=16, Dh=64.  kqv chunk order per reference: k, q, v.
// Round 2: projection GEMMs on tensor cores (tf32 mma.sync), attention fp32.
// ---------------------------------------------------------------------------

#define B_DIM 4
#define S_DIM 2048
#define D_DIM 1024
#define H_DIM 16
#define DH_DIM 64

// scratch (allocation-free rule: __device__ globals)
__device__ float g_kqv[B_DIM * S_DIM * 3 * D_DIM];   // [B,S,3D]
__device__ float g_attn[B_DIM * S_DIM * D_DIM];      // [B,S,D]

// ---------------------------------------------------------------------------
// tf32 helpers
// ---------------------------------------------------------------------------
__device__ __forceinline__ unsigned f2tf32(float f) {
    unsigned r;
    asm("cvt.rna.tf32.f32 %0, %1;" : "=r"(r) : "f"(f));
    return r;
}

__device__ __forceinline__ void mma_tf32(float c[4],
                                         unsigned a0, unsigned a1, unsigned a2, unsigned a3,
                                         unsigned b0, unsigned b1)
{
    asm volatile(
        "mma.sync.aligned.m16n8k8.row.col.f32.tf32.tf32.f32 "
        "{%0,%1,%2,%3}, {%4,%5,%6,%7}, {%8,%9}, {%0,%1,%2,%3};"
        : "+f"(c[0]), "+f"(c[1]), "+f"(c[2]), "+f"(c[3])
        : "r"(a0), "r"(a1), "r"(a2), "r"(a3), "r"(b0), "r"(b1));
}

// ---------------------------------------------------------------------------
// TF32 GEMM: C[M,N] = A[M,K] @ B[K,N] + bias[N]
// 128x128x32 CTA tile, 256 threads (8 warps), 64x32 warp tile = 4x4 m16n8k8.
// ---------------------------------------------------------------------------
__global__ void __launch_bounds__(256)
gemm_tf32_kernel(const float* __restrict__ A, const float* __restrict__ Bmat,
                 const float* __restrict__ bias, float* __restrict__ C,
                 int M, int N, int K)
{
    const int BK = 32;
    __shared__ unsigned As[32][132];   // [k][m], padded (132*4=528B row, 16B-mult)
    __shared__ unsigned Bs[32][132];   // [k][n], padded

    const int tid  = threadIdx.x;
    const int warp = tid >> 5;
    const int lane = tid & 31;
    const int row0 = blockIdx.y * 128;
    const int col0 = blockIdx.x * 128;

    const int wm = warp >> 2;          // 0..1
    const int wn = warp & 3;           // 0..3
    const int row_w = wm * 64;         // warp row offset in tile
    const int col_w = wn * 32;         // warp col offset in tile
    const int grp = lane >> 2;         // 0..7
    const int tig = lane & 3;          // 0..3

    float acc[4][4][4];
    #pragma unroll
    for (int mt = 0; mt < 4; mt++)
        #pragma unroll
        for (int nt = 0; nt < 4; nt++)
            #pragma unroll
            for (int r = 0; r < 4; r++) acc[mt][nt][r] = 0.f;

    for (int k0 = 0; k0 < K; k0 += BK) {
        // A tile: 128 rows x 32 k. 1024 float4 loads, 4 per thread.
        #pragma unroll
        for (int i = 0; i < 4; i++) {
            int idx = tid + i * 256;            // 0..1023
            int r   = idx >> 3;                 // 0..127
            int kq  = (idx & 7) << 2;           // 0,4,...,28
            float4 v = *(const float4*)&A[(size_t)(row0 + r) * K + k0 + kq];
            As[kq + 0][r] = f2tf32(v.x);
            As[kq + 1][r] = f2tf32(v.y);
            As[kq + 2][r] = f2tf32(v.z);
            As[kq + 3][r] = f2tf32(v.w);
        }
        // B tile: 32 k-rows x 128 n.
        #pragma unroll
        for (int i = 0; i < 4; i++) {
            int idx = tid + i * 256;
            int kr  = idx >> 5;                 // 0..31
            int nc  = (idx & 31) << 2;          // 0..124
            float4 v = *(const float4*)&Bmat[(size_t)(k0 + kr) * N + col0 + nc];
            uint4 t;
            t.x = f2tf32(v.x); t.y = f2tf32(v.y);
            t.z = f2tf32(v.z); t.w = f2tf32(v.w);
            *(uint4*)&Bs[kr][nc] = t;
        }
        __syncthreads();

        #pragma unroll
        for (int ks = 0; ks < 4; ks++) {
            const int kk = ks * 8;
            unsigned af[4][4];
            #pragma unroll
            for (int mt = 0; mt < 4; mt++) {
                int m = row_w + mt * 16;
                af[mt][0] = As[kk + tig    ][m + grp];
                af[mt][1] = As[kk + tig    ][m + 8 + grp];
                af[mt][2] = As[kk + 4 + tig][m + grp];
                af[mt][3] = As[kk + 4 + tig][m + 8 + grp];
            }
            unsigned bf[4][2];
            #pragma unroll
            for (int nt = 0; nt < 4; nt++) {
                int n = col_w + nt * 8;
                bf[nt][0] = Bs[kk + tig    ][n + grp];
                bf[nt][1] = Bs[kk + 4 + tig][n + grp];
            }
            #pragma unroll
            for (int mt = 0; mt < 4; mt++)
                #pragma unroll
                for (int nt = 0; nt < 4; nt++)
                    mma_tf32(acc[mt][nt],
                             af[mt][0], af[mt][1], af[mt][2], af[mt][3],
                             bf[nt][0], bf[nt][1]);
        }
        __syncthreads();
    }

    // epilogue: bias + store (float2 per half-fragment)
    #pragma unroll
    for (int mt = 0; mt < 4; mt++) {
        #pragma unroll
        for (int nt = 0; nt < 4; nt++) {
            int m = row0 + row_w + mt * 16;
            int n = col0 + col_w + nt * 8 + tig * 2;
            float b0 = bias[n], b1 = bias[n + 1];
            float2 v0, v1;
            v0.x = acc[mt][nt][0] + b0; v0.y = acc[mt][nt][1] + b1;
            v1.x = acc[mt][nt][2] + b0; v1.y = acc[mt][nt][3] + b1;
            *(float2*)&C[(size_t)(m + grp) * N + n]     = v0;
            *(float2*)&C[(size_t)(m + 8 + grp) * N + n] = v1;
        }
    }
}

// ---------------------------------------------------------------------------
// Attention: one CTA = 128 query rows of one (b,h). Online softmax over KV
// tiles of 32. q/o in registers; K/V tiles in smem (broadcast reads).
// ---------------------------------------------------------------------------
__global__ void __launch_bounds__(128)
attn_kernel(const float* __restrict__ kqv, float* __restrict__ out)
{
    const int TK = 32;
    __shared__ float Ks[32][64];
    __shared__ float Vs[32][64];
    __shared__ float Ss[128][33];

    const int tid  = threadIdx.x;
    const int b    = blockIdx.z;
    const int h    = blockIdx.y;
    const int qrow = blockIdx.x * 128 + tid;
    const int D3   = 3 * D_DIM;
    const float scale = 0.125f;      // 1/sqrt(64)

    float q[64], o[64];
    {
        const float* qp = kqv + (size_t)(b * S_DIM + qrow) * D3 + D_DIM + h * DH_DIM;
        #pragma unroll
        for (int d = 0; d < 64; d += 4) {
            float4 v = *(const float4*)(qp + d);
            q[d + 0] = v.x * scale; q[d + 1] = v.y * scale;
            q[d + 2] = v.z * scale; q[d + 3] = v.w * scale;
            o[d + 0] = 0.f; o[d + 1] = 0.f; o[d + 2] = 0.f; o[d + 3] = 0.f;
        }
    }

    float m = -1e30f, l = 0.f;

    for (int t0 = 0; t0 < S_DIM; t0 += TK) {
        __syncthreads();
        #pragma unroll
        for (int i = 0; i < 4; i++) {
            int lin = tid + i * 128;
            int r   = lin >> 4;
            int c   = (lin & 15) << 2;
            size_t base = (size_t)(b * S_DIM + t0 + r) * D3 + h * DH_DIM + c;
            *(float4*)&Ks[r][c] = *(const float4*)(kqv + base);
            *(float4*)&Vs[r][c] = *(const float4*)(kqv + base + 2 * D_DIM);
        }
        __syncthreads();

        float mt = -1e30f;
        #pragma unroll 4
        for (int j = 0; j < TK; j++) {
            float acc = 0.f;
            #pragma unroll
            for (int d = 0; d < 64; d += 4) {
                float4 kv = *(const float4*)&Ks[j][d];
                acc += q[d] * kv.x + q[d + 1] * kv.y
                     + q[d + 2] * kv.z + q[d + 3] * kv.w;
            }
            Ss[tid][j] = acc;
            mt = fmaxf(mt, acc);
        }

        float mn   = fmaxf(m, mt);
        float corr = __expf(m - mn);
        m = mn;
        l *= corr;
        #pragma unroll
        for (int d = 0; d < 64; d++) o[d] *= corr;

        #pragma unroll 2
        for (int j = 0; j < TK; j++) {
            float p = __expf(Ss[tid][j] - mn);
            l += p;
            #pragma unroll
            for (int d = 0; d < 64; d += 4) {
                float4 vv = *(const float4*)&Vs[j][d];
                o[d + 0] += p * vv.x; o[d + 1] += p * vv.y;
                o[d + 2] += p * vv.z; o[d + 3] += p * vv.w;
            }
        }
    }

    float inv = 1.f / l;
    float* op = out + (size_t)(b * S_DIM + qrow) * D_DIM + h * DH_DIM;
    #pragma unroll
    for (int d = 0; d < 64; d += 4) {
        float4 v;
        v.x = o[d + 0] * inv; v.y = o[d + 1] * inv;
        v.z = o[d + 2] * inv; v.w = o[d + 3] * inv;
        *(float4*)(op + d) = v;
    }
}

// ---------------------------------------------------------------------------
extern "C" void kernel_launch(void* const* d_in, const int* in_sizes, int n_in,
                              void* d_out, int out_size)
{
    const float* x     = (const float*)d_in[0];   // [4,2048,1024]
    const float* w_in  = (const float*)d_in[1];   // [1024,3072]
    const float* b_in  = (const float*)d_in[2];   // [3072]
    const float* w_out = (const float*)d_in[3];   // [1024,1024]
    const float* b_out = (const float*)d_in[4];   // [1024]
    float* out = (float*)d_out;

    float *kqv, *attn;
    cudaGetSymbolAddress((void**)&kqv, g_kqv);
    cudaGetSymbolAddress((void**)&attn, g_attn);

    const int M = B_DIM * S_DIM;                  // 8192

    // 1) kqv = x @ w_in + b_in     [8192, 3072]
    {
        dim3 grid(3 * D_DIM / 128, M / 128);
        gemm_tf32_kernel<<<grid, 256>>>(x, w_in, b_in, kqv, M, 3 * D_DIM, D_DIM);
    }
    // 2) attention -> g_attn [B,S,D]
    {
        dim3 grid(S_DIM / 128, H_DIM, B_DIM);
        attn_kernel<<<grid, 128>>>(kqv, attn);
    }
    // 3) out = attn @ w_out + b_out  [8192, 1024]
    {
        dim3 grid(D_DIM / 128, M / 128);
        gemm_tf32_kernel<<<grid, 256>>>(attn, w_out, b_out, out, M, D_DIM, D_DIM);
    }
}

// round 4
// speedup vs baseline: 3.5145x; 2.8648x over previous
#include <cuda_runtime.h>
#include <math.h>

// ---------------------------------------------------------------------------
// SelfAttention: out = softmax((Q K^T)/sqrt(Dh)) V  with fused QKV + out proj
// B=4, S=2048, D=1024, H=16, Dh=64.  kqv chunk order per reference: k, q, v.
// Round 3: tf32 tensor cores everywhere; conflict-free smem bank mappings.
// ---------------------------------------------------------------------------

#define B_DIM 4
#define S_DIM 2048
#define D_DIM 1024
#define H_DIM 16
#define DH_DIM 64

__device__ float g_kqv[B_DIM * S_DIM * 3 * D_DIM];   // [B,S,3D]
__device__ float g_attn[B_DIM * S_DIM * D_DIM];      // [B,S,D]

// ---------------------------------------------------------------------------
__device__ __forceinline__ unsigned f2tf32(float f) {
    unsigned r;
    asm("cvt.rna.tf32.f32 %0, %1;" : "=r"(r) : "f"(f));
    return r;
}

__device__ __forceinline__ void mma_tf32(float c[4],
                                         unsigned a0, unsigned a1, unsigned a2, unsigned a3,
                                         unsigned b0, unsigned b1)
{
    asm volatile(
        "mma.sync.aligned.m16n8k8.row.col.f32.tf32.tf32.f32 "
        "{%0,%1,%2,%3}, {%4,%5,%6,%7}, {%8,%9}, {%0,%1,%2,%3};"
        : "+f"(c[0]), "+f"(c[1]), "+f"(c[2]), "+f"(c[3])
        : "r"(a0), "r"(a1), "r"(a2), "r"(a3), "r"(b0), "r"(b1));
}

// ---------------------------------------------------------------------------
// TF32 GEMM: C[M,N] = A[M,K] @ B[K,N] + bias[N]
// 128x128x32 CTA tile, 256 threads (8 warps), 64x32 warp tile = 4x4 m16n8k8.
// As natural [m][k] stride 36 (bank = 4*grp+tig, bijective).
// Bs [k][n] stride 136 (bank = 8*tig+grp, bijective). Conflict-free.
// ---------------------------------------------------------------------------
__global__ void __launch_bounds__(256)
gemm_tf32_kernel(const float* __restrict__ A, const float* __restrict__ Bmat,
                 const float* __restrict__ bias, float* __restrict__ C,
                 int M, int N, int K)
{
    const int BK = 32;
    __shared__ unsigned As[128][36];   // [m][k] padded
    __shared__ unsigned Bs[32][136];   // [k][n] padded

    const int tid  = threadIdx.x;
    const int warp = tid >> 5;
    const int lane = tid & 31;
    const int row0 = blockIdx.y * 128;
    const int col0 = blockIdx.x * 128;

    const int wm = warp >> 2;          // 0..1
    const int wn = warp & 3;           // 0..3
    const int row_w = wm * 64;
    const int col_w = wn * 32;
    const int grp = lane >> 2;         // 0..7
    const int tig = lane & 3;          // 0..3

    float acc[4][4][4];
    #pragma unroll
    for (int mt = 0; mt < 4; mt++)
        #pragma unroll
        for (int nt = 0; nt < 4; nt++)
            #pragma unroll
            for (int r = 0; r < 4; r++) acc[mt][nt][r] = 0.f;

    for (int k0 = 0; k0 < K; k0 += BK) {
        // A tile: 128 rows x 32 k, natural layout. 4 uint4 stores per thread.
        #pragma unroll
        for (int i = 0; i < 4; i++) {
            int idx = tid + i * 256;            // 0..1023
            int r   = idx >> 3;                 // 0..127
            int kc  = (idx & 7) << 2;           // 0,4,...,28
            float4 v = *(const float4*)&A[(size_t)(row0 + r) * K + k0 + kc];
            uint4 t;
            t.x = f2tf32(v.x); t.y = f2tf32(v.y);
            t.z = f2tf32(v.z); t.w = f2tf32(v.w);
            *(uint4*)&As[r][kc] = t;
        }
        // B tile: 32 k-rows x 128 n.
        #pragma unroll
        for (int i = 0; i < 4; i++) {
            int idx = tid + i * 256;
            int kr  = idx >> 5;                 // 0..31
            int nc  = (idx & 31) << 2;          // 0..124
            float4 v = *(const float4*)&Bmat[(size_t)(k0 + kr) * N + col0 + nc];
            uint4 t;
            t.x = f2tf32(v.x); t.y = f2tf32(v.y);
            t.z = f2tf32(v.z); t.w = f2tf32(v.w);
            *(uint4*)&Bs[kr][nc] = t;
        }
        __syncthreads();

        #pragma unroll
        for (int ks = 0; ks < 4; ks++) {
            const int kk = ks * 8;
            unsigned af[4][4];
            #pragma unroll
            for (int mt = 0; mt < 4; mt++) {
                int m = row_w + mt * 16;
                af[mt][0] = As[m + grp    ][kk + tig];
                af[mt][1] = As[m + 8 + grp][kk + tig];
                af[mt][2] = As[m + grp    ][kk + 4 + tig];
                af[mt][3] = As[m + 8 + grp][kk + 4 + tig];
            }
            unsigned bf[4][2];
            #pragma unroll
            for (int nt = 0; nt < 4; nt++) {
                int n = col_w + nt * 8;
                bf[nt][0] = Bs[kk + tig    ][n + grp];
                bf[nt][1] = Bs[kk + 4 + tig][n + grp];
            }
            #pragma unroll
            for (int mt = 0; mt < 4; mt++)
                #pragma unroll
                for (int nt = 0; nt < 4; nt++)
                    mma_tf32(acc[mt][nt],
                             af[mt][0], af[mt][1], af[mt][2], af[mt][3],
                             bf[nt][0], bf[nt][1]);
        }
        __syncthreads();
    }

    #pragma unroll
    for (int mt = 0; mt < 4; mt++) {
        #pragma unroll
        for (int nt = 0; nt < 4; nt++) {
            int m = row0 + row_w + mt * 16;
            int n = col0 + col_w + nt * 8 + tig * 2;
            float b0 = bias[n], b1 = bias[n + 1];
            float2 v0, v1;
            v0.x = acc[mt][nt][0] + b0; v0.y = acc[mt][nt][1] + b1;
            v1.x = acc[mt][nt][2] + b0; v1.y = acc[mt][nt][3] + b1;
            *(float2*)&C[(size_t)(m + grp) * N + n]     = v0;
            *(float2*)&C[(size_t)(m + 8 + grp) * N + n] = v1;
        }
    }
}

// ---------------------------------------------------------------------------
// Tensor-core flash attention. CTA: 128 q-rows of one (b,h), 8 warps.
// Warp w owns q rows [w*16, w*16+16). KV tiles of 32 keys.
// K stored naturally Kn[key][d] (stride 68): B-frag (k=d,n=key) = Kn[n][k],
// bank = 4*grp+tig (bijective). Vs[key][d] stride 72: bank = 8*tig+grp.
// P staged per-warp in Ps stride 36: bank = 4*grp+tig.
// ---------------------------------------------------------------------------
__global__ void __launch_bounds__(256)
attn_tc_kernel(const float* __restrict__ kqv, float* __restrict__ out)
{
    __shared__ unsigned Kn[32][68];      // [key][d]
    __shared__ unsigned Vs[32][72];      // [key][d]
    __shared__ unsigned Ps[8][16][36];   // [warp][qrow][key]

    const int tid  = threadIdx.x;
    const int warp = tid >> 5;
    const int lane = tid & 31;
    const int grp  = lane >> 2;          // 0..7
    const int tig  = lane & 3;           // 0..3
    const int b    = blockIdx.z;
    const int h    = blockIdx.y;
    const int qrow0 = blockIdx.x * 128;
    const int D3   = 3 * D_DIM;
    const float scale = 0.125f;          // 1/sqrt(64)

    const int row_lo = qrow0 + warp * 16 + grp;
    const int row_hi = row_lo + 8;

    // Q fragments (chunk order k,q,v -> q at +D), pre-scaled, tf32
    unsigned qa[8][4];
    {
        const float* qlo = kqv + (size_t)(b * S_DIM + row_lo) * D3 + D_DIM + h * DH_DIM;
        const float* qhi = kqv + (size_t)(b * S_DIM + row_hi) * D3 + D_DIM + h * DH_DIM;
        #pragma unroll
        for (int ks = 0; ks < 8; ks++) {
            int c = ks * 8 + tig;
            qa[ks][0] = f2tf32(qlo[c]     * scale);
            qa[ks][1] = f2tf32(qhi[c]     * scale);
            qa[ks][2] = f2tf32(qlo[c + 4] * scale);
            qa[ks][3] = f2tf32(qhi[c + 4] * scale);
        }
    }

    float o[8][4];
    #pragma unroll
    for (int nt = 0; nt < 8; nt++)
        #pragma unroll
        for (int r = 0; r < 4; r++) o[nt][r] = 0.f;

    float m_lo = -1e30f, m_hi = -1e30f, lp_lo = 0.f, lp_hi = 0.f;

    for (int t0 = 0; t0 < S_DIM; t0 += 32) {
        __syncthreads();
        // Load K,V tile: 32 keys x 64 dh each, natural layout, coalesced.
        #pragma unroll
        for (int i = 0; i < 2; i++) {
            int lin = tid + i * 256;         // 0..511
            int key = lin >> 4;              // 0..31
            int c4  = (lin & 15) << 2;       // 0..60
            size_t base = (size_t)(b * S_DIM + t0 + key) * D3 + h * DH_DIM + c4;
            float4 kv = *(const float4*)(kqv + base);               // K at +0
            float4 vv = *(const float4*)(kqv + base + 2 * D_DIM);   // V at +2D
            uint4 tk, tv;
            tk.x = f2tf32(kv.x); tk.y = f2tf32(kv.y);
            tk.z = f2tf32(kv.z); tk.w = f2tf32(kv.w);
            tv.x = f2tf32(vv.x); tv.y = f2tf32(vv.y);
            tv.z = f2tf32(vv.z); tv.w = f2tf32(vv.w);
            *(uint4*)&Kn[key][c4] = tk;
            *(uint4*)&Vs[key][c4] = tv;
        }
        __syncthreads();

        // S = Q K^T for this warp's 16 rows x 32 keys
        float s[4][4];
        #pragma unroll
        for (int nt = 0; nt < 4; nt++) {
            #pragma unroll
            for (int r = 0; r < 4; r++) s[nt][r] = 0.f;
            #pragma unroll
            for (int ks = 0; ks < 8; ks++) {
                int kk = ks * 8;
                unsigned b0 = Kn[nt * 8 + grp][kk + tig];
                unsigned b1 = Kn[nt * 8 + grp][kk + 4 + tig];
                mma_tf32(s[nt], qa[ks][0], qa[ks][1], qa[ks][2], qa[ks][3], b0, b1);
            }
        }

        // row max (rows grp -> lo, grp+8 -> hi), quad-reduce over tig
        float rl = -1e30f, rh = -1e30f;
        #pragma unroll
        for (int nt = 0; nt < 4; nt++) {
            rl = fmaxf(rl, fmaxf(s[nt][0], s[nt][1]));
            rh = fmaxf(rh, fmaxf(s[nt][2], s[nt][3]));
        }
        rl = fmaxf(rl, __shfl_xor_sync(0xffffffffu, rl, 1));
        rl = fmaxf(rl, __shfl_xor_sync(0xffffffffu, rl, 2));
        rh = fmaxf(rh, __shfl_xor_sync(0xffffffffu, rh, 1));
        rh = fmaxf(rh, __shfl_xor_sync(0xffffffffu, rh, 2));

        float mn_lo = fmaxf(m_lo, rl);
        float mn_hi = fmaxf(m_hi, rh);
        float corr_lo = __expf(m_lo - mn_lo);
        float corr_hi = __expf(m_hi - mn_hi);
        m_lo = mn_lo; m_hi = mn_hi;
        lp_lo *= corr_lo; lp_hi *= corr_hi;
        #pragma unroll
        for (int nt = 0; nt < 8; nt++) {
            o[nt][0] *= corr_lo; o[nt][1] *= corr_lo;
            o[nt][2] *= corr_hi; o[nt][3] *= corr_hi;
        }

        // P = exp(S - m), accumulate partial l, stage to Ps (tf32)
        #pragma unroll
        for (int nt = 0; nt < 4; nt++) {
            float p0 = __expf(s[nt][0] - mn_lo);
            float p1 = __expf(s[nt][1] - mn_lo);
            float p2 = __expf(s[nt][2] - mn_hi);
            float p3 = __expf(s[nt][3] - mn_hi);
            lp_lo += p0 + p1;
            lp_hi += p2 + p3;
            int c = nt * 8 + tig * 2;
            Ps[warp][grp    ][c]     = f2tf32(p0);
            Ps[warp][grp    ][c + 1] = f2tf32(p1);
            Ps[warp][grp + 8][c]     = f2tf32(p2);
            Ps[warp][grp + 8][c + 1] = f2tf32(p3);
        }
        __syncwarp();

        // O += P V
        #pragma unroll
        for (int ks = 0; ks < 4; ks++) {
            int kk = ks * 8;
            unsigned a0 = Ps[warp][grp    ][kk + tig];
            unsigned a1 = Ps[warp][grp + 8][kk + tig];
            unsigned a2 = Ps[warp][grp    ][kk + 4 + tig];
            unsigned a3 = Ps[warp][grp + 8][kk + 4 + tig];
            #pragma unroll
            for (int nt = 0; nt < 8; nt++) {
                unsigned b0 = Vs[kk + tig    ][nt * 8 + grp];
                unsigned b1 = Vs[kk + 4 + tig][nt * 8 + grp];
                mma_tf32(o[nt], a0, a1, a2, a3, b0, b1);
            }
        }
    }

    // final: full-row l, normalize, write out
    lp_lo += __shfl_xor_sync(0xffffffffu, lp_lo, 1);
    lp_lo += __shfl_xor_sync(0xffffffffu, lp_lo, 2);
    lp_hi += __shfl_xor_sync(0xffffffffu, lp_hi, 1);
    lp_hi += __shfl_xor_sync(0xffffffffu, lp_hi, 2);
    float inv_lo = 1.f / lp_lo;
    float inv_hi = 1.f / lp_hi;

    float* olo = out + (size_t)(b * S_DIM + row_lo) * D_DIM + h * DH_DIM;
    float* ohi = out + (size_t)(b * S_DIM + row_hi) * D_DIM + h * DH_DIM;
    #pragma unroll
    for (int nt = 0; nt < 8; nt++) {
        int c = nt * 8 + tig * 2;
        float2 vlo, vhi;
        vlo.x = o[nt][0] * inv_lo; vlo.y = o[nt][1] * inv_lo;
        vhi.x = o[nt][2] * inv_hi; vhi.y = o[nt][3] * inv_hi;
        *(float2*)(olo + c) = vlo;
        *(float2*)(ohi + c) = vhi;
    }
}

// ---------------------------------------------------------------------------
extern "C" void kernel_launch(void* const* d_in, const int* in_sizes, int n_in,
                              void* d_out, int out_size)
{
    const float* x     = (const float*)d_in[0];   // [4,2048,1024]
    const float* w_in  = (const float*)d_in[1];   // [1024,3072]
    const float* b_in  = (const float*)d_in[2];   // [3072]
    const float* w_out = (const float*)d_in[3];   // [1024,1024]
    const float* b_out = (const float*)d_in[4];   // [1024]
    float* out = (float*)d_out;

    float *kqv, *attn;
    cudaGetSymbolAddress((void**)&kqv, g_kqv);
    cudaGetSymbolAddress((void**)&attn, g_attn);

    const int M = B_DIM * S_DIM;                  // 8192

    // 1) kqv = x @ w_in + b_in     [8192, 3072]
    {
        dim3 grid(3 * D_DIM / 128, M / 128);
        gemm_tf32_kernel<<<grid, 256>>>(x, w_in, b_in, kqv, M, 3 * D_DIM, D_DIM);
    }
    // 2) attention -> g_attn [B,S,D]
    {
        dim3 grid(S_DIM / 128, H_DIM, B_DIM);
        attn_tc_kernel<<<grid, 256>>>(kqv, attn);
    }
    // 3) out = attn @ w_out + b_out  [8192, 1024]
    {
        dim3 grid(D_DIM / 128, M / 128);
        gemm_tf32_kernel<<<grid, 256>>>(attn, w_out, b_out, out, M, D_DIM, D_DIM);
    }
}